// round 2
// baseline (speedup 1.0000x reference)
#include <cuda_runtime.h>

#define TT 32
#define BB 2048
#define DD 64
#define WWID 256
#define MROWS 16
#define NCTA (BB / MROWS)   // 128
#define NTHR 256

// Transposed weights, [k][n] layout so weight loads are lane-coalesced.
__device__ float g_W0t[DD * WWID];    // 64 x 256
__device__ float g_W1t[WWID * WWID];  // 256 x 256
__device__ float g_W2t[WWID * DD];    // 256 x 64

__global__ void prep_kernel(const float* __restrict__ W0,
                            const float* __restrict__ W1,
                            const float* __restrict__ W2) {
    int idx = blockIdx.x * blockDim.x + threadIdx.x;
    if (idx < DD * WWID) {              // W0t[k][n] = W0[n][k], k<64, n<256
        int k = idx >> 8, n = idx & 255;
        g_W0t[idx] = W0[n * DD + k];
    }
    if (idx < WWID * WWID) {            // W1t[k][n] = W1[n][k]
        int k = idx >> 8, n = idx & 255;
        g_W1t[idx] = W1[n * WWID + k];
    }
    if (idx < WWID * DD) {              // W2t[k][d] = W2[d][k], k<256, d<64
        int k = idx >> 6, d = idx & 63;
        g_W2t[idx] = W2[d * WWID + k];
    }
}

__device__ __forceinline__ float tanh_fast(float x) {
    // exact identity tanh(x) = 1 - 2/(e^{2x}+1); ~1e-6 abs err with fast exp/div
    float e = __expf(2.0f * x);
    return 1.0f - __fdividef(2.0f, e + 1.0f);
}

__device__ __forceinline__ void ld4(float* d, const float* p) {
    float4 t = *reinterpret_cast<const float4*>(p);
    d[0] = t.x; d[1] = t.y; d[2] = t.z; d[3] = t.w;
}

__device__ __forceinline__ float4 f4fma(float4 a, float s, float4 b) {
    a.x = fmaf(s, b.x, a.x); a.y = fmaf(s, b.y, a.y);
    a.z = fmaf(s, b.z, a.z); a.w = fmaf(s, b.w, a.w);
    return a;
}

// Hidden layer: out[16][256] = tanh(x[16][K] @ Wt(K x 256) + bias), 256 threads.
// Thread tile: 4 rows x 4 cols. A-loads are warp-broadcast LDS.128,
// W-loads are coalesced LDG.128 from the transposed [k][n] weights.
__device__ __forceinline__ void dense_h(const float* __restrict__ x, int K,
                                        const float* __restrict__ Wt,
                                        const float* __restrict__ bias,
                                        float* __restrict__ o, int tid) {
    const int r0 = (tid >> 6) << 2;   // 0,4,8,12
    const int c0 = (tid & 63) << 2;   // 0..252
    float acc[4][4];
    {
        float4 bv = *reinterpret_cast<const float4*>(bias + c0);
        #pragma unroll
        for (int r = 0; r < 4; ++r) {
            acc[r][0] = bv.x; acc[r][1] = bv.y; acc[r][2] = bv.z; acc[r][3] = bv.w;
        }
    }
    const float* xp0 = x + r0 * K;
    const float* xp1 = xp0 + K;
    const float* xp2 = xp1 + K;
    const float* xp3 = xp2 + K;
    const float* wp = Wt + c0;
    #pragma unroll 2
    for (int k = 0; k < K; k += 4) {
        float a[4][4];   // [r][kk]
        float w[4][4];   // [kk][c]
        ld4(a[0], xp0 + k); ld4(a[1], xp1 + k);
        ld4(a[2], xp2 + k); ld4(a[3], xp3 + k);
        ld4(w[0], wp);        ld4(w[1], wp + 256);
        ld4(w[2], wp + 512);  ld4(w[3], wp + 768);
        wp += 1024;
        #pragma unroll
        for (int r = 0; r < 4; ++r)
            #pragma unroll
            for (int kk = 0; kk < 4; ++kk)
                #pragma unroll
                for (int c = 0; c < 4; ++c)
                    acc[r][c] = fmaf(a[r][kk], w[kk][c], acc[r][c]);
    }
    #pragma unroll
    for (int r = 0; r < 4; ++r) {
        float4 v;
        v.x = tanh_fast(acc[r][0]); v.y = tanh_fast(acc[r][1]);
        v.z = tanh_fast(acc[r][2]); v.w = tanh_fast(acc[r][3]);
        *reinterpret_cast<float4*>(o + (r0 + r) * WWID + c0) = v;
    }
}

// Output layer: k[16][64] = (x[16][256] @ W2t(256 x 64) + b2) * efac
// Thread tile: 1 row x 4 cols (16 col-groups x 16 rows = 256 threads).
__device__ __forceinline__ void dense_o(const float* __restrict__ x,
                                        const float* __restrict__ Wt,
                                        const float* __restrict__ bias,
                                        float* __restrict__ o, float efac, int tid) {
    const int row = tid >> 4;         // 0..15
    const int c0 = (tid & 15) << 2;   // 0..60
    float acc[4];
    {
        float4 bv = *reinterpret_cast<const float4*>(bias + c0);
        acc[0] = bv.x; acc[1] = bv.y; acc[2] = bv.z; acc[3] = bv.w;
    }
    const float* xp = x + row * WWID;
    const float* wp = Wt + c0;
    #pragma unroll 2
    for (int k = 0; k < WWID; k += 4) {
        float a[4];
        float w[4][4];
        ld4(a, xp + k);
        ld4(w[0], wp);       ld4(w[1], wp + 64);
        ld4(w[2], wp + 128); ld4(w[3], wp + 192);
        wp += 256;
        #pragma unroll
        for (int kk = 0; kk < 4; ++kk)
            #pragma unroll
            for (int c = 0; c < 4; ++c)
                acc[c] = fmaf(a[kk], w[kk][c], acc[c]);
    }
    float4 v;
    v.x = acc[0] * efac; v.y = acc[1] * efac;
    v.z = acc[2] * efac; v.w = acc[3] * efac;
    *reinterpret_cast<float4*>(o + row * DD + c0) = v;
}

// smem layout (floats)
#define OFF_SY   0
#define OFF_SYT  (OFF_SY + MROWS * DD)        // 1024
#define OFF_SH0  (OFF_SYT + MROWS * DD)       // 2048
#define OFF_SH1  (OFF_SH0 + MROWS * WWID)     // 6144
#define OFF_SK   (OFF_SH1 + MROWS * WWID)     // 10240
#define OFF_SB0  (OFF_SK + 6 * MROWS * DD)    // 16384
#define OFF_SB1  (OFF_SB0 + WWID)             // 16640
#define OFF_SB2  (OFF_SB1 + WWID)             // 16896
#define OFF_STS  (OFF_SB2 + DD)               // 16960
#define SMEM_FLOATS (OFF_STS + TT)            // 16992

__global__ void __launch_bounds__(NTHR)
ode_kernel(const float* __restrict__ ts, const float* __restrict__ y0,
           const float* __restrict__ b0, const float* __restrict__ b1,
           const float* __restrict__ b2, float* __restrict__ out) {
    extern __shared__ float sm[];
    float* sy  = sm + OFF_SY;
    float* syt = sm + OFF_SYT;
    float* sh0 = sm + OFF_SH0;
    float* sh1 = sm + OFF_SH1;
    float* sk  = sm + OFF_SK;
    float* sb0 = sm + OFF_SB0;
    float* sb1 = sm + OFF_SB1;
    float* sb2 = sm + OFF_SB2;
    float* sts = sm + OFF_STS;

    const int tid = threadIdx.x;
    const int rb = blockIdx.x * MROWS;

    // Init: load y0 slice, biases, ts; write t=0 output slice.
    {
        float4 v = reinterpret_cast<const float4*>(y0)[rb * (DD / 4) + tid];
        reinterpret_cast<float4*>(sy)[tid] = v;
        reinterpret_cast<float4*>(out)[rb * (DD / 4) + tid] = v;
        sb0[tid] = b0[tid];
        sb1[tid] = b1[tid];
        if (tid < DD) sb2[tid] = b2[tid];
        if (tid < TT) sts[tid] = ts[tid];
    }
    __syncthreads();

    float4* sy4  = reinterpret_cast<float4*>(sy);
    float4* syt4 = reinterpret_cast<float4*>(syt);
    float4* k14  = reinterpret_cast<float4*>(sk + 0 * MROWS * DD);
    float4* k24  = reinterpret_cast<float4*>(sk + 1 * MROWS * DD);
    float4* k34  = reinterpret_cast<float4*>(sk + 2 * MROWS * DD);
    float4* k44  = reinterpret_cast<float4*>(sk + 3 * MROWS * DD);
    float4* k54  = reinterpret_cast<float4*>(sk + 4 * MROWS * DD);
    float4* k64  = reinterpret_cast<float4*>(sk + 5 * MROWS * DD);

    for (int iv = 0; iv < TT - 1; ++iv) {
        const float t0 = sts[iv];
        const float dt = sts[iv + 1] - t0;
        const float h = 0.5f * dt;

        for (int sub = 0; sub < 2; ++sub) {
            const float tc = t0 + (float)sub * h;

            // ---- stage 1: k1 = vf(tc, y) ----
            dense_h(sy, DD, g_W0t, sb0, sh0, tid);  __syncthreads();
            dense_h(sh0, WWID, g_W1t, sb1, sh1, tid); __syncthreads();
            dense_o(sh1, g_W2t, sb2, sk + 0 * MROWS * DD, __expf(tc), tid); __syncthreads();

            // ---- stage 2 ----
            {
                float4 v = f4fma(sy4[tid], h * 0.2f, k14[tid]);
                syt4[tid] = v;
            }
            __syncthreads();
            dense_h(syt, DD, g_W0t, sb0, sh0, tid);  __syncthreads();
            dense_h(sh0, WWID, g_W1t, sb1, sh1, tid); __syncthreads();
            dense_o(sh1, g_W2t, sb2, sk + 1 * MROWS * DD, __expf(tc + 0.2f * h), tid); __syncthreads();

            // ---- stage 3 ----
            {
                float4 v = sy4[tid];
                v = f4fma(v, h * (3.0f / 40.0f), k14[tid]);
                v = f4fma(v, h * (9.0f / 40.0f), k24[tid]);
                syt4[tid] = v;
            }
            __syncthreads();
            dense_h(syt, DD, g_W0t, sb0, sh0, tid);  __syncthreads();
            dense_h(sh0, WWID, g_W1t, sb1, sh1, tid); __syncthreads();
            dense_o(sh1, g_W2t, sb2, sk + 2 * MROWS * DD, __expf(tc + 0.3f * h), tid); __syncthreads();

            // ---- stage 4 ----
            {
                float4 v = sy4[tid];
                v = f4fma(v, h * (44.0f / 45.0f),  k14[tid]);
                v = f4fma(v, h * (-56.0f / 15.0f), k24[tid]);
                v = f4fma(v, h * (32.0f / 9.0f),   k34[tid]);
                syt4[tid] = v;
            }
            __syncthreads();
            dense_h(syt, DD, g_W0t, sb0, sh0, tid);  __syncthreads();
            dense_h(sh0, WWID, g_W1t, sb1, sh1, tid); __syncthreads();
            dense_o(sh1, g_W2t, sb2, sk + 3 * MROWS * DD, __expf(tc + 0.8f * h), tid); __syncthreads();

            // ---- stage 5 ----
            {
                float4 v = sy4[tid];
                v = f4fma(v, h * (19372.0f / 6561.0f),  k14[tid]);
                v = f4fma(v, h * (-25360.0f / 2187.0f), k24[tid]);
                v = f4fma(v, h * (64448.0f / 6561.0f),  k34[tid]);
                v = f4fma(v, h * (-212.0f / 729.0f),    k44[tid]);
                syt4[tid] = v;
            }
            __syncthreads();
            dense_h(syt, DD, g_W0t, sb0, sh0, tid);  __syncthreads();
            dense_h(sh0, WWID, g_W1t, sb1, sh1, tid); __syncthreads();
            dense_o(sh1, g_W2t, sb2, sk + 4 * MROWS * DD, __expf(tc + (8.0f / 9.0f) * h), tid); __syncthreads();

            // ---- stage 6 ----
            {
                float4 v = sy4[tid];
                v = f4fma(v, h * (9017.0f / 3168.0f),   k14[tid]);
                v = f4fma(v, h * (-355.0f / 33.0f),     k24[tid]);
                v = f4fma(v, h * (46732.0f / 5247.0f),  k34[tid]);
                v = f4fma(v, h * (49.0f / 176.0f),      k44[tid]);
                v = f4fma(v, h * (-5103.0f / 18656.0f), k54[tid]);
                syt4[tid] = v;
            }
            __syncthreads();
            dense_h(syt, DD, g_W0t, sb0, sh0, tid);  __syncthreads();
            dense_h(sh0, WWID, g_W1t, sb1, sh1, tid); __syncthreads();
            dense_o(sh1, g_W2t, sb2, sk + 5 * MROWS * DD, __expf(tc + h), tid); __syncthreads();

            // ---- final combine ----
            {
                float4 v = sy4[tid];
                v = f4fma(v, h * (35.0f / 384.0f),     k14[tid]);
                v = f4fma(v, h * (500.0f / 1113.0f),   k34[tid]);
                v = f4fma(v, h * (125.0f / 192.0f),    k44[tid]);
                v = f4fma(v, h * (-2187.0f / 6784.0f), k54[tid]);
                v = f4fma(v, h * (11.0f / 84.0f),      k64[tid]);
                sy4[tid] = v;
            }
            __syncthreads();
        }

        // write output slice (iv+1)
        {
            float4 v = sy4[tid];
            reinterpret_cast<float4*>(out)[((iv + 1) * BB + rb) * (DD / 4) + tid] = v;
        }
    }
}

extern "C" void kernel_launch(void* const* d_in, const int* in_sizes, int n_in,
                              void* d_out, int out_size) {
    const float* ts = (const float*)d_in[0];
    const float* y0 = (const float*)d_in[1];
    const float* W0 = (const float*)d_in[2];
    const float* b0 = (const float*)d_in[3];
    const float* W1 = (const float*)d_in[4];
    const float* b1 = (const float*)d_in[5];
    const float* W2 = (const float*)d_in[6];
    const float* b2 = (const float*)d_in[7];
    float* out = (float*)d_out;

    prep_kernel<<<256, 256>>>(W0, W1, W2);

    size_t smem_bytes = SMEM_FLOATS * sizeof(float);
    cudaFuncSetAttribute(ode_kernel, cudaFuncAttributeMaxDynamicSharedMemorySize,
                         (int)smem_bytes);
    ode_kernel<<<NCTA, NTHR, smem_bytes>>>(ts, y0, b0, b1, b2, out);
}